// round 1
// baseline (speedup 1.0000x reference)
#include <cuda_runtime.h>

#define LH 128
#define LP 32
#define DM 64
#define HID 64
#define NH 4
#define HD 16
#define MAXLEN 128
#define XPAD 68   // padded row stride (floats): 16B-aligned, conflict-free LDS.128 phases

// smem layout (floats)
#define S_X_OFF   0
#define S_PEP_OFF (LH*XPAD)
#define S_KV_OFF  (LH*XPAD + LP*XPAD)
#define SMEM_FLOATS (LH*XPAD + LP*XPAD + LP*HID)
#define SMEM_BYTES (SMEM_FLOATS * 4)

#define FMA4(A, B0, S, W)                      \
    do {                                       \
        A[(B0)+0] = fmaf((S), (W).x, A[(B0)+0]); \
        A[(B0)+1] = fmaf((S), (W).y, A[(B0)+1]); \
        A[(B0)+2] = fmaf((S), (W).z, A[(B0)+2]); \
        A[(B0)+3] = fmaf((S), (W).w, A[(B0)+3]); \
    } while (0)

__global__ __launch_bounds__(128, 2)
void h2p_kernel(const float* __restrict__ hla_in,
                const float* __restrict__ pep_in,
                const float* __restrict__ W_hla, const float* __restrict__ b_hla,
                const float* __restrict__ W_pep, const float* __restrict__ b_pep,
                const float* __restrict__ rel_bias,
                const float* __restrict__ ln_g, const float* __restrict__ ln_b,
                const float* __restrict__ W1, const float* __restrict__ b1,
                const float* __restrict__ W2, const float* __restrict__ b2,
                const float* __restrict__ W_out, const float* __restrict__ b_out,
                float* __restrict__ out)
{
    extern __shared__ float sm[];
    float* s_x   = sm + S_X_OFF;    // [128][XPAD]: hla input -> projected hla -> residual z
    float* s_pep = sm + S_PEP_OFF;  // [32][XPAD]:  pep input
    float* s_kv  = sm + S_KV_OFF;   // [32][64]:    projected kv

    const int t = threadIdx.x;
    const int b = blockIdx.x;
    const float* hla_b = hla_in + (size_t)b * (LH * DM);
    const float* pep_b = pep_in + (size_t)b * (LP * DM);

    // ---------- stage pep input [32][64] (coalesced) ----------
    {
        const float4* g4 = (const float4*)pep_b;
        #pragma unroll
        for (int j = 0; j < 4; j++) {
            int v = j * 128 + t;           // float4 index, 16 per row
            float4 d = g4[v];
            int r = v >> 4, c4 = v & 15;
            *(float4*)&s_pep[r * XPAD + c4 * 4] = d;
        }
    }
    // ---------- stage hla input [128][64] (coalesced) ----------
    {
        const float4* g4 = (const float4*)hla_b;
        #pragma unroll
        for (int j = 0; j < 16; j++) {
            int v = j * 128 + t;
            float4 d = g4[v];
            int r = v >> 4, c4 = v & 15;
            *(float4*)&s_x[r * XPAD + c4 * 4] = d;
        }
    }
    __syncthreads();

    // ---------- kv = pep @ W_pep + b_pep -> s_kv [32][64] ----------
    // warp cg handles column group cg*16..+15, lane r handles row r
    {
        const int cg = t >> 5;
        const int r  = t & 31;
        const int c0 = cg * 16;
        float acc[16];
        #pragma unroll
        for (int m = 0; m < 4; m++) {
            float4 bv = __ldg((const float4*)&b_pep[c0 + m * 4]);
            acc[m*4+0] = bv.x; acc[m*4+1] = bv.y; acc[m*4+2] = bv.z; acc[m*4+3] = bv.w;
        }
        #pragma unroll 1
        for (int k0 = 0; k0 < DM; k0 += 4) {
            float4 x4 = *(const float4*)&s_pep[r * XPAD + k0];
            float xs[4] = {x4.x, x4.y, x4.z, x4.w};
            #pragma unroll
            for (int kk = 0; kk < 4; kk++) {
                #pragma unroll
                for (int m = 0; m < 4; m++) {
                    float4 w = __ldg((const float4*)&W_pep[(k0 + kk) * HID + c0 + m * 4]);
                    FMA4(acc, m * 4, xs[kk], w);
                }
            }
        }
        #pragma unroll
        for (int m = 0; m < 4; m++)
            *(float4*)&s_kv[r * HID + c0 + m * 4] =
                make_float4(acc[m*4+0], acc[m*4+1], acc[m*4+2], acc[m*4+3]);
    }

    // ---------- q = hla row t @ W_hla + b_hla (kept in regs + parked in s_x) ----------
    float q[64];
    {
        #pragma unroll
        for (int c4 = 0; c4 < 16; c4++) {
            float4 bv = __ldg((const float4*)&b_hla[c4 * 4]);
            q[c4*4+0] = bv.x; q[c4*4+1] = bv.y; q[c4*4+2] = bv.z; q[c4*4+3] = bv.w;
        }
        #pragma unroll 1
        for (int k0 = 0; k0 < DM; k0 += 4) {
            float4 x4 = *(const float4*)&s_x[t * XPAD + k0];
            float xs[4] = {x4.x, x4.y, x4.z, x4.w};
            #pragma unroll
            for (int kk = 0; kk < 4; kk++) {
                #pragma unroll
                for (int c4 = 0; c4 < 16; c4++) {
                    float4 w = __ldg((const float4*)&W_hla[(k0 + kk) * HID + c4 * 4]);
                    FMA4(q, c4 * 4, xs[kk], w);
                }
            }
        }
        // park projected hla for the residual (frees q regs after attention)
        #pragma unroll
        for (int c4 = 0; c4 < 16; c4++)
            *(float4*)&s_x[t * XPAD + c4 * 4] =
                make_float4(q[c4*4+0], q[c4*4+1], q[c4*4+2], q[c4*4+3]);
    }
    __syncthreads();   // kv visible to all

    // ---------- attention: thread t = query row t, 4 heads, Lp=32 keys ----------
    float ctx[64];
    #pragma unroll
    for (int h = 0; h < NH; h++) {
        const float* bias_row = rel_bias + h * (MAXLEN * MAXLEN) + t * MAXLEN;
        float sc[32];
        #pragma unroll
        for (int k4 = 0; k4 < 8; k4++) {
            float4 bv = __ldg((const float4*)(bias_row + k4 * 4));
            sc[k4*4+0] = bv.x; sc[k4*4+1] = bv.y; sc[k4*4+2] = bv.z; sc[k4*4+3] = bv.w;
        }
        #pragma unroll
        for (int k = 0; k < LP; k++) {
            const float* kvr = &s_kv[k * HID + h * HD];
            float4 a0 = *(const float4*)(kvr + 0);
            float4 a1 = *(const float4*)(kvr + 4);
            float4 a2 = *(const float4*)(kvr + 8);
            float4 a3 = *(const float4*)(kvr + 12);
            float d;
            d = q[h*HD+0] * a0.x;
            d = fmaf(q[h*HD+1],  a0.y, d);
            d = fmaf(q[h*HD+2],  a0.z, d);
            d = fmaf(q[h*HD+3],  a0.w, d);
            d = fmaf(q[h*HD+4],  a1.x, d);
            d = fmaf(q[h*HD+5],  a1.y, d);
            d = fmaf(q[h*HD+6],  a1.z, d);
            d = fmaf(q[h*HD+7],  a1.w, d);
            d = fmaf(q[h*HD+8],  a2.x, d);
            d = fmaf(q[h*HD+9],  a2.y, d);
            d = fmaf(q[h*HD+10], a2.z, d);
            d = fmaf(q[h*HD+11], a2.w, d);
            d = fmaf(q[h*HD+12], a3.x, d);
            d = fmaf(q[h*HD+13], a3.y, d);
            d = fmaf(q[h*HD+14], a3.z, d);
            d = fmaf(q[h*HD+15], a3.w, d);
            sc[k] = fmaf(0.25f, d, sc[k]);   // scale = 1/sqrt(16)
        }
        // softmax over 32 keys
        float mx = sc[0];
        #pragma unroll
        for (int k = 1; k < LP; k++) mx = fmaxf(mx, sc[k]);
        float ssum = 0.f;
        #pragma unroll
        for (int k = 0; k < LP; k++) { sc[k] = __expf(sc[k] - mx); ssum += sc[k]; }
        float inv = 1.0f / ssum;
        float a[16];
        #pragma unroll
        for (int d2 = 0; d2 < 16; d2++) a[d2] = 0.f;
        #pragma unroll
        for (int k = 0; k < LP; k++) {
            const float* kvr = &s_kv[k * HID + h * HD];
            float4 a0 = *(const float4*)(kvr + 0);
            float4 a1 = *(const float4*)(kvr + 4);
            float4 a2 = *(const float4*)(kvr + 8);
            float4 a3 = *(const float4*)(kvr + 12);
            float p = sc[k];
            FMA4(a, 0,  p, a0);
            FMA4(a, 4,  p, a1);
            FMA4(a, 8,  p, a2);
            FMA4(a, 12, p, a3);
        }
        #pragma unroll
        for (int d2 = 0; d2 < 16; d2++) ctx[h*HD+d2] = a[d2] * inv;
    }

    // ---------- LayerNorm (over 64) ----------
    {
        float mu = 0.f;
        #pragma unroll
        for (int c = 0; c < HID; c++) mu += ctx[c];
        mu *= (1.0f / 64.0f);
        float var = 0.f;
        #pragma unroll
        for (int c = 0; c < HID; c++) { float d = ctx[c] - mu; var = fmaf(d, d, var); }
        var *= (1.0f / 64.0f);
        float rstd = rsqrtf(var + 1e-5f);
        #pragma unroll
        for (int c4 = 0; c4 < 16; c4++) {
            float4 gv = __ldg((const float4*)&ln_g[c4 * 4]);
            float4 bv = __ldg((const float4*)&ln_b[c4 * 4]);
            ctx[c4*4+0] = (ctx[c4*4+0] - mu) * rstd * gv.x + bv.x;
            ctx[c4*4+1] = (ctx[c4*4+1] - mu) * rstd * gv.y + bv.y;
            ctx[c4*4+2] = (ctx[c4*4+2] - mu) * rstd * gv.z + bv.z;
            ctx[c4*4+3] = (ctx[c4*4+3] - mu) * rstd * gv.w + bv.w;
        }
    }

    // ---------- FFN: gelu(ctx @ W1 + b1) @ W2 + b2 ----------
    float acc[64];
    #pragma unroll
    for (int c4 = 0; c4 < 16; c4++) {
        float4 bv = __ldg((const float4*)&b2[c4 * 4]);
        acc[c4*4+0] = bv.x; acc[c4*4+1] = bv.y; acc[c4*4+2] = bv.z; acc[c4*4+3] = bv.w;
    }
    #pragma unroll 1
    for (int i0 = 0; i0 < 2 * HID; i0 += 4) {
        float4 gb = __ldg((const float4*)&b1[i0]);
        float g0 = gb.x, g1 = gb.y, g2 = gb.z, g3 = gb.w;
        #pragma unroll
        for (int k = 0; k < HID; k++) {
            float4 w = __ldg((const float4*)&W1[k * (2 * HID) + i0]);
            g0 = fmaf(ctx[k], w.x, g0);
            g1 = fmaf(ctx[k], w.y, g1);
            g2 = fmaf(ctx[k], w.z, g2);
            g3 = fmaf(ctx[k], w.w, g3);
        }
        // exact gelu: x * Phi(x)
        g0 *= normcdff(g0); g1 *= normcdff(g1); g2 *= normcdff(g2); g3 *= normcdff(g3);
        float gm[4] = {g0, g1, g2, g3};
        #pragma unroll
        for (int m = 0; m < 4; m++) {
            #pragma unroll
            for (int j4 = 0; j4 < 16; j4++) {
                float4 w = __ldg((const float4*)&W2[(i0 + m) * HID + j4 * 4]);
                FMA4(acc, j4 * 4, gm[m], w);
            }
        }
    }

    // ---------- residual z = hla + ffn (write back into s_x row t) ----------
    #pragma unroll
    for (int c4 = 0; c4 < 16; c4++) {
        float4 hv = *(const float4*)&s_x[t * XPAD + c4 * 4];
        hv.x += acc[c4*4+0]; hv.y += acc[c4*4+1]; hv.z += acc[c4*4+2]; hv.w += acc[c4*4+3];
        *(float4*)&s_x[t * XPAD + c4 * 4] = hv;
    }

    // ---------- out = z @ W_out + b_out ----------
    float y[64];
    #pragma unroll
    for (int c4 = 0; c4 < 16; c4++) {
        float4 bv = __ldg((const float4*)&b_out[c4 * 4]);
        y[c4*4+0] = bv.x; y[c4*4+1] = bv.y; y[c4*4+2] = bv.z; y[c4*4+3] = bv.w;
    }
    #pragma unroll 1
    for (int k0 = 0; k0 < HID; k0 += 4) {
        float4 z4 = *(const float4*)&s_x[t * XPAD + k0];
        float zs[4] = {z4.x, z4.y, z4.z, z4.w};
        #pragma unroll
        for (int kk = 0; kk < 4; kk++) {
            #pragma unroll
            for (int c4 = 0; c4 < 16; c4++) {
                float4 w = __ldg((const float4*)&W_out[(k0 + kk) * DM + c4 * 4]);
                FMA4(y, c4 * 4, zs[kk], w);
            }
        }
    }
    float* op = out + ((size_t)b * LH + t) * DM;
    #pragma unroll
    for (int c4 = 0; c4 < 16; c4++)
        *(float4*)&op[c4 * 4] = make_float4(y[c4*4+0], y[c4*4+1], y[c4*4+2], y[c4*4+3]);
}

extern "C" void kernel_launch(void* const* d_in, const int* in_sizes, int n_in,
                              void* d_out, int out_size)
{
    const float* hla_in   = (const float*)d_in[0];
    const float* pep_in   = (const float*)d_in[1];
    const float* W_hla    = (const float*)d_in[2];
    const float* b_hla    = (const float*)d_in[3];
    const float* W_pep    = (const float*)d_in[4];
    const float* b_pep    = (const float*)d_in[5];
    const float* rel_bias = (const float*)d_in[6];
    const float* ln_g     = (const float*)d_in[7];
    const float* ln_b     = (const float*)d_in[8];
    const float* W1       = (const float*)d_in[9];
    const float* b1       = (const float*)d_in[10];
    const float* W2       = (const float*)d_in[11];
    const float* b2       = (const float*)d_in[12];
    const float* W_out    = (const float*)d_in[13];
    const float* b_out    = (const float*)d_in[14];
    float* out = (float*)d_out;

    int B = in_sizes[0] / (LH * DM);

    cudaFuncSetAttribute(h2p_kernel, cudaFuncAttributeMaxDynamicSharedMemorySize, SMEM_BYTES);
    h2p_kernel<<<B, 128, SMEM_BYTES>>>(hla_in, pep_in, W_hla, b_hla, W_pep, b_pep,
                                       rel_bias, ln_g, ln_b, W1, b1, W2, b2,
                                       W_out, b_out, out);
}